// round 11
// baseline (speedup 1.0000x reference)
#include <cuda_runtime.h>
#include <cuda_bf16.h>
#include <cstdint>

#define TPB   512
#define M_CTA 256

// ---------------- smem map (bytes; regions 1024-aligned) ----------------
#define OFF_BIAS 0          // 160 floats
#define OFF_W1H  1024       // 4 segs x [64k][64n] bf16, 8192 B each
#define OFF_W1L  33792
#define OFF_W2H  66560
#define OFF_W2L  74752
#define OFF_W3H  82944      // padded to n=64
#define OFF_W3L  91136
#define STAGE_BYTES 99328   // [0, STAGE_BYTES) is the precomputed image
#define OFF_X0H  99328      // X buffer 0: [256 rows][64 cols] bf16 hi
#define OFF_X0L  132096
#define OFF_X1H  164864     // X buffer 1
#define OFF_X1L  197632
#define SMEM_TOTAL 230400

#define SWZ128(bo) ((bo) ^ (((bo) >> 3) & 0x70))

__device__ __align__(1024) unsigned char g_stage[STAGE_BYTES];
__device__ int g_is64;

// ---------------- PTX wrappers ----------------
__device__ __forceinline__ uint32_t smem_u32(const void* p) {
    uint32_t a;
    asm("{ .reg .u64 t; cvta.to.shared.u64 t, %1; cvt.u32.u64 %0, t; }" : "=r"(a) : "l"(p));
    return a;
}
__device__ __forceinline__ void ldsm4(uint32_t r[4], uint32_t a) {
    asm volatile("ldmatrix.sync.aligned.m8n8.x4.shared.b16 {%0,%1,%2,%3}, [%4];"
        : "=r"(r[0]), "=r"(r[1]), "=r"(r[2]), "=r"(r[3]) : "r"(a));
}
__device__ __forceinline__ void ldsm4t(uint32_t r[4], uint32_t a) {
    asm volatile("ldmatrix.sync.aligned.m8n8.x4.trans.shared.b16 {%0,%1,%2,%3}, [%4];"
        : "=r"(r[0]), "=r"(r[1]), "=r"(r[2]), "=r"(r[3]) : "r"(a));
}
__device__ __forceinline__ void mma16816(float c[4], const uint32_t a[4], const uint32_t b[2]) {
    asm volatile("mma.sync.aligned.m16n8k16.row.col.f32.bf16.bf16.f32 "
        "{%0,%1,%2,%3}, {%4,%5,%6,%7}, {%8,%9}, {%0,%1,%2,%3};"
        : "+f"(c[0]), "+f"(c[1]), "+f"(c[2]), "+f"(c[3])
        : "r"(a[0]), "r"(a[1]), "r"(a[2]), "r"(a[3]), "r"(b[0]), "r"(b[1]));
}

// ---------------- numeric helpers ----------------
__device__ __forceinline__ uint32_t pack_hi2(float a, float b) {
    return (__float_as_uint(a) >> 16) | (__float_as_uint(b) & 0xFFFF0000u);
}
__device__ __forceinline__ uint32_t pack_lo2(float a, float b) {
    float ra = a - __uint_as_float(__float_as_uint(a) & 0xFFFF0000u);
    float rb = b - __uint_as_float(__float_as_uint(b) & 0xFFFF0000u);
    return (__float_as_uint(ra) >> 16) | (__float_as_uint(rb) & 0xFFFF0000u);
}
__device__ __forceinline__ float softplus_f(float v) {
    return fmaxf(v, 0.0f) + __logf(1.0f + __expf(-fabsf(v)));
}

// ---------------------------------------------------------------------------
// precompute split-bf16 swizzled weight image + biases; block 0 also detects
// index dtype (int64 vs int32) from odd 32-bit words of atom_idx.
__global__ void stage_weights(const float* __restrict__ W1, const float* __restrict__ b1,
                              const float* __restrict__ W2, const float* __restrict__ b2,
                              const float* __restrict__ W3, const float* __restrict__ b3,
                              const unsigned int* __restrict__ idxprobe) {
    if (blockIdx.x == 0 && threadIdx.x < 32) {
        unsigned ok = __ballot_sync(0xFFFFFFFFu, idxprobe[2 * threadIdx.x + 1] == 0u);
        if (threadIdx.x == 0) g_is64 = (ok == 0xFFFFFFFFu);
    }
    int t = blockIdx.x * blockDim.x + threadIdx.x;
    unsigned char* st = g_stage;
    if (t < 16384) {                       // W1 [256k][64n]
        int n = t & 63, k = t >> 6;
        float v = W1[t];
        int s = k >> 6, kl = k & 63;
        uint32_t bo = SWZ128((uint32_t)(kl * 128 + n * 2));
        float r = v - __uint_as_float(__float_as_uint(v) & 0xFFFF0000u);
        *(unsigned short*)(st + OFF_W1H + s * 8192 + bo) = (unsigned short)(__float_as_uint(v) >> 16);
        *(unsigned short*)(st + OFF_W1L + s * 8192 + bo) = (unsigned short)(__float_as_uint(r) >> 16);
    } else if (t < 20480) {                // W2 [64][64]
        int i = t - 16384;
        int n = i & 63, k = i >> 6;
        float v = W2[i];
        uint32_t bo = SWZ128((uint32_t)(k * 128 + n * 2));
        float r = v - __uint_as_float(__float_as_uint(v) & 0xFFFF0000u);
        *(unsigned short*)(st + OFF_W2H + bo) = (unsigned short)(__float_as_uint(v) >> 16);
        *(unsigned short*)(st + OFF_W2L + bo) = (unsigned short)(__float_as_uint(r) >> 16);
    } else if (t < 24576) {                // W3 [64][32] padded to n=64
        int i = t - 20480;
        int n = i & 63, k = i >> 6;
        float v = (n < 32) ? W3[k * 32 + n] : 0.0f;
        uint32_t bo = SWZ128((uint32_t)(k * 128 + n * 2));
        float r = v - __uint_as_float(__float_as_uint(v) & 0xFFFF0000u);
        *(unsigned short*)(st + OFF_W3H + bo) = (unsigned short)(__float_as_uint(v) >> 16);
        *(unsigned short*)(st + OFF_W3L + bo) = (unsigned short)(__float_as_uint(r) >> 16);
    } else if (t < 24576 + 64) {
        ((float*)(st + OFF_BIAS))[t - 24576] = b1[t - 24576];
    } else if (t < 24576 + 128) {
        ((float*)(st + OFF_BIAS))[t - 24576] = b2[t - 24640];
    } else if (t < 24576 + 160) {
        ((float*)(st + OFF_BIAS))[t - 24576] = b3[t - 24704];
    }
}

// ---------------- cooperative gather (512 threads; lb 0..31, part 0..15) -----
struct GatherCtx {
    const float* bond; const float* atom; const float* glob;
    const void* aidx; const void* gidx;
    int n_bond; int is64; int lb; int part;
};

template<int SEG>
__device__ __forceinline__ void load_chunk(const GatherCtx& c, long long base,
                                           int r0, float4 v[4]) {
    #pragma unroll
    for (int i = 0; i < 4; i++) {
        const int bl = (r0 + i) * 32 + c.lb;
        const long long gb = base + bl;
        const size_t bond = (size_t)((gb < c.n_bond) ? gb : (c.n_bond - 1));
        size_t row; const float* bp;
        if (SEG == 0) { row = bond; bp = c.bond; }
        else if (SEG == 3) {
            row = c.is64 ? (size_t)((const long long*)c.gidx)[bond]
                         : (size_t)((const int*)c.gidx)[bond];
            bp = c.glob;
        } else {
            row = c.is64 ? (size_t)((const long long*)c.aidx)[2 * bond + (SEG - 1)]
                         : (size_t)((const int*)c.aidx)[2 * bond + (SEG - 1)];
            bp = c.atom;
        }
        v[i] = ((const float4*)(bp + row * 64))[c.part];
    }
}

__device__ __forceinline__ void sts_chunk(char* smem, uint32_t offH, uint32_t offL,
                                          int lb, int part, int r0, const float4 v[4]) {
    #pragma unroll
    for (int i = 0; i < 4; i++) {
        const int bl = (r0 + i) * 32 + lb;
        const uint32_t bo = SWZ128((uint32_t)(bl * 128 + part * 8));
        uint64_t hi = ((uint64_t)pack_hi2(v[i].z, v[i].w) << 32) | pack_hi2(v[i].x, v[i].y);
        uint64_t lo = ((uint64_t)pack_lo2(v[i].z, v[i].w) << 32) | pack_lo2(v[i].x, v[i].y);
        *(uint64_t*)(smem + offH + bo) = hi;
        *(uint64_t*)(smem + offL + bo) = lo;
    }
}

// ---------------- warp-level GEMM (M=16), A from smem: kt in [KT0, KT1) ------
template<int NT, int KT0, int KT1>
__device__ __forceinline__ void gemm_part(uint32_t sb,
                                          uint32_t offAH, uint32_t offAL,
                                          uint32_t offBH, uint32_t offBL,
                                          int m0, int lane, float acc[][4]) {
    #pragma unroll
    for (int kt = KT0; kt < KT1; kt++) {
        const int k0 = kt * 16;
        uint32_t ah[4], al[4];
        {
            int row = m0 + (lane & 15);
            uint32_t bo = (uint32_t)(row * 128 + k0 * 2 + ((lane >> 4) << 4));
            ldsm4(ah, sb + offAH + SWZ128(bo));
            ldsm4(al, sb + offAL + SWZ128(bo));
        }
        #pragma unroll
        for (int nb = 0; nb < NT / 2; nb++) {
            uint32_t bh[4], bl[4];
            int krow = k0 + (lane & 15);
            uint32_t bo = (uint32_t)(krow * 128 + nb * 32 + ((lane >> 4) << 4));
            ldsm4t(bh, sb + offBH + SWZ128(bo));
            ldsm4t(bl, sb + offBL + SWZ128(bo));
            #pragma unroll
            for (int h = 0; h < 2; h++) {
                const uint32_t bfh[2] = { bh[2 * h], bh[2 * h + 1] };
                const uint32_t bfl[2] = { bl[2 * h], bl[2 * h + 1] };
                const int nt = nb * 2 + h;
                mma16816(acc[nt], ah, bfh);
                mma16816(acc[nt], ah, bfl);
                mma16816(acc[nt], al, bfh);
            }
        }
    }
}

// ---------------- warp-level GEMM (M=16), A from packed registers ------------
template<int NT, int KT0, int KT1>
__device__ __forceinline__ void gemm_regA(uint32_t sb,
                                          const uint32_t aph[4][4], const uint32_t alp[4][4],
                                          uint32_t offBH, uint32_t offBL,
                                          int lane, float acc[][4]) {
    #pragma unroll
    for (int kt = KT0; kt < KT1; kt++) {
        const int k0 = kt * 16;
        #pragma unroll
        for (int nb = 0; nb < NT / 2; nb++) {
            uint32_t bh[4], bl[4];
            int krow = k0 + (lane & 15);
            uint32_t bo = (uint32_t)(krow * 128 + nb * 32 + ((lane >> 4) << 4));
            ldsm4t(bh, sb + offBH + SWZ128(bo));
            ldsm4t(bl, sb + offBL + SWZ128(bo));
            #pragma unroll
            for (int h2 = 0; h2 < 2; h2++) {
                const uint32_t bfh[2] = { bh[2 * h2], bh[2 * h2 + 1] };
                const uint32_t bfl[2] = { bl[2 * h2], bl[2 * h2 + 1] };
                const int nt = nb * 2 + h2;
                mma16816(acc[nt], aph[kt], bfh);
                mma16816(acc[nt], aph[kt], bfl);
                mma16816(acc[nt], alp[kt], bfh);
            }
        }
    }
}

// bias + softplus in place on 8 C-fragments (M=16 warp tile)
__device__ __forceinline__ void act_inplace8(float acc[][4], const float* bias, int lane) {
    #pragma unroll
    for (int i = 0; i < 8; i++) {
        const int col = i * 8 + (lane & 3) * 2;
        const float b0 = bias[col], b1 = bias[col + 1];
        acc[i][0] = softplus_f(acc[i][0] + b0);
        acc[i][1] = softplus_f(acc[i][1] + b1);
        acc[i][2] = softplus_f(acc[i][2] + b0);
        acc[i][3] = softplus_f(acc[i][3] + b1);
    }
}

// pack 8 activated C-fragments (64 cols) into split-bf16 A-fragments per kt
__device__ __forceinline__ void pack_h(const float acc[][4],
                                       uint32_t aph[4][4], uint32_t alp[4][4]) {
    #pragma unroll
    for (int kt = 0; kt < 4; kt++) {
        const float* t0 = acc[2 * kt];
        const float* t1 = acc[2 * kt + 1];
        aph[kt][0] = pack_hi2(t0[0], t0[1]);
        aph[kt][1] = pack_hi2(t0[2], t0[3]);
        aph[kt][2] = pack_hi2(t1[0], t1[1]);
        aph[kt][3] = pack_hi2(t1[2], t1[3]);
        alp[kt][0] = pack_lo2(t0[0], t0[1]);
        alp[kt][1] = pack_lo2(t0[2], t0[3]);
        alp[kt][2] = pack_lo2(t1[0], t1[1]);
        alp[kt][3] = pack_lo2(t1[2], t1[3]);
    }
}

// ---------------------------------------------------------------------------
__global__ __launch_bounds__(TPB, 1)
void bond_mlp_mma(const float* __restrict__ bond_feats,
                  const float* __restrict__ atom_feats,
                  const float* __restrict__ global_feats,
                  const void*  __restrict__ atom_idx,
                  const void*  __restrict__ global_idx,
                  float* __restrict__ out, int n_bond)
{
    extern __shared__ char smem[];
    const uint32_t sb = smem_u32(smem);
    const int tid  = threadIdx.x;
    const int wid  = tid >> 5;
    const int lane = tid & 31;
    const int m0   = wid * 16;       // 16 warps x 16 rows = 256

    GatherCtx ctx;
    ctx.bond = bond_feats; ctx.atom = atom_feats; ctx.glob = global_feats;
    ctx.aidx = atom_idx;   ctx.gidx = global_idx;
    ctx.n_bond = n_bond;   ctx.is64 = g_is64;
    ctx.lb = tid >> 4;     ctx.part = tid & 15;

    const long long ntiles = (n_bond + M_CTA - 1) / M_CTA;
    long long tile = blockIdx.x;
    long long base = tile * M_CTA;

    float4 v[4];

    // prologue: seg0 of first tile LDGs in flight during the one-time weight copy
    load_chunk<0>(ctx, base, 0, v);
    {
        const float4* src = (const float4*)g_stage;
        float4* dst = (float4*)smem;
        #pragma unroll 4
        for (int i = tid; i < STAGE_BYTES / 16; i += TPB) dst[i] = src[i];
    }
    sts_chunk(smem, OFF_X0H, OFF_X0L, ctx.lb, ctx.part, 0, v);
    load_chunk<0>(ctx, base, 4, v);
    sts_chunk(smem, OFF_X0H, OFF_X0L, ctx.lb, ctx.part, 4, v);
    __syncthreads();

    // persistent tile loop; invariant on entry: X0 holds seg0 of `tile`, synced
    #pragma unroll 1
    while (true) {
        float acc[8][4];
        #pragma unroll
        for (int i = 0; i < 8; i++)
            #pragma unroll
            for (int q = 0; q < 4; q++) acc[i][q] = 0.0f;

        // ---- L1 seg0 (reads X0, prefetch seg1 -> X1) ----
        load_chunk<1>(ctx, base, 0, v);
        gemm_part<8, 0, 2>(sb, OFF_X0H, OFF_X0L, OFF_W1H, OFF_W1L, m0, lane, acc);
        sts_chunk(smem, OFF_X1H, OFF_X1L, ctx.lb, ctx.part, 0, v);
        load_chunk<1>(ctx, base, 4, v);
        gemm_part<8, 2, 4>(sb, OFF_X0H, OFF_X0L, OFF_W1H, OFF_W1L, m0, lane, acc);
        sts_chunk(smem, OFF_X1H, OFF_X1L, ctx.lb, ctx.part, 4, v);
        __syncthreads();

        // ---- seg1 (reads X1, prefetch seg2 -> X0) ----
        load_chunk<2>(ctx, base, 0, v);
        gemm_part<8, 0, 2>(sb, OFF_X1H, OFF_X1L, OFF_W1H + 8192, OFF_W1L + 8192, m0, lane, acc);
        sts_chunk(smem, OFF_X0H, OFF_X0L, ctx.lb, ctx.part, 0, v);
        load_chunk<2>(ctx, base, 4, v);
        gemm_part<8, 2, 4>(sb, OFF_X1H, OFF_X1L, OFF_W1H + 8192, OFF_W1L + 8192, m0, lane, acc);
        sts_chunk(smem, OFF_X0H, OFF_X0L, ctx.lb, ctx.part, 4, v);
        __syncthreads();

        // ---- seg2 (reads X0, prefetch seg3 -> X1) ----
        load_chunk<3>(ctx, base, 0, v);
        gemm_part<8, 0, 2>(sb, OFF_X0H, OFF_X0L, OFF_W1H + 16384, OFF_W1L + 16384, m0, lane, acc);
        sts_chunk(smem, OFF_X1H, OFF_X1L, ctx.lb, ctx.part, 0, v);
        load_chunk<3>(ctx, base, 4, v);
        gemm_part<8, 2, 4>(sb, OFF_X0H, OFF_X0L, OFF_W1H + 16384, OFF_W1L + 16384, m0, lane, acc);
        sts_chunk(smem, OFF_X1H, OFF_X1L, ctx.lb, ctx.part, 4, v);
        __syncthreads();

        // ---- seg3 (reads X1) ----
        gemm_part<8, 0, 4>(sb, OFF_X1H, OFF_X1L, OFF_W1H + 24576, OFF_W1L + 24576, m0, lane, acc);

        // ---- h1 = softplus(acc + b1); pack to split-bf16 fragments ----
        act_inplace8(acc, (const float*)(smem + OFF_BIAS), lane);
        uint32_t aph[4][4], alp[4][4];
        pack_h(acc, aph, alp);          // acc dead after this

        // ---- L2 (A from registers); prefetch next tile seg0 -> X0 ----------
        const long long ntile = tile + gridDim.x;
        const bool more = (ntile < ntiles);
        const long long nbase = ntile * M_CTA;

        float acc2[8][4];
        #pragma unroll
        for (int i = 0; i < 8; i++)
            #pragma unroll
            for (int q = 0; q < 4; q++) acc2[i][q] = 0.0f;

        if (more) load_chunk<0>(ctx, nbase, 0, v);
        gemm_regA<8, 0, 2>(sb, aph, alp, OFF_W2H, OFF_W2L, lane, acc2);
        if (more) { sts_chunk(smem, OFF_X0H, OFF_X0L, ctx.lb, ctx.part, 0, v);
                    load_chunk<0>(ctx, nbase, 4, v); }
        gemm_regA<8, 2, 4>(sb, aph, alp, OFF_W2H, OFF_W2L, lane, acc2);
        if (more) sts_chunk(smem, OFF_X0H, OFF_X0L, ctx.lb, ctx.part, 4, v);

        // ---- h2 = softplus(acc2 + b2); pack ----
        act_inplace8(acc2, (const float*)(smem + OFF_BIAS) + 64, lane);
        pack_h(acc2, aph, alp);         // reuse fragment regs

        // ---- L3 (A from registers, N=32) ----
        float acc3[4][4];
        #pragma unroll
        for (int i = 0; i < 4; i++)
            #pragma unroll
            for (int q = 0; q < 4; q++) acc3[i][q] = 0.0f;
        gemm_regA<4, 0, 4>(sb, aph, alp, OFF_W3H, OFF_W3L, lane, acc3);

        // ---- output: acc3 + b3 -> global ----
        {
            const float* bias = (const float*)(smem + OFF_BIAS) + 128;
            #pragma unroll
            for (int nt = 0; nt < 4; nt++) {
                const int col = nt * 8 + (lane & 3) * 2;
                const float bv0 = bias[col], bv1 = bias[col + 1];
                #pragma unroll
                for (int h = 0; h < 2; h++) {
                    const int row = m0 + (lane >> 2) + h * 8;
                    const long long gb = base + row;
                    if (gb < n_bond) {
                        float2 o = make_float2(acc3[nt][2 * h]     + bv0,
                                               acc3[nt][2 * h + 1] + bv1);
                        *(float2*)(out + (size_t)gb * 32 + col) = o;
                    }
                }
            }
        }

        if (!more) break;
        tile = ntile; base = nbase;
        __syncthreads();   // X0 (next seg0) visible; X1 seg3 reads complete
    }
}

// ---------------------------------------------------------------------------
extern "C" void kernel_launch(void* const* d_in, const int* in_sizes, int n_in,
                              void* d_out, int out_size)
{
    const float* bond_feats   = (const float*)d_in[0];
    const float* atom_feats   = (const float*)d_in[1];
    const float* global_feats = (const float*)d_in[2];
    const void*  atom_idx     = d_in[3];
    const void*  global_idx   = d_in[4];
    const float* W1 = (const float*)d_in[5];
    const float* b1 = (const float*)d_in[6];
    const float* W2 = (const float*)d_in[7];
    const float* b2 = (const float*)d_in[8];
    const float* W3 = (const float*)d_in[9];
    const float* b3 = (const float*)d_in[10];
    float* out = (float*)d_out;

    const int n_bond = in_sizes[0] / 64;
    const long long ntiles = (n_bond + M_CTA - 1) / M_CTA;

    static int smCount = 0;
    if (!smCount) {
        cudaFuncSetAttribute(bond_mlp_mma,
                             cudaFuncAttributeMaxDynamicSharedMemorySize, SMEM_TOTAL);
        cudaDeviceGetAttribute(&smCount, cudaDevAttrMultiProcessorCount, 0);
        if (smCount <= 0) smCount = 148;
    }

    stage_weights<<<97, 256>>>(W1, b1, W2, b2, W3, b3, (const unsigned int*)atom_idx);

    const int grid = (int)((ntiles < smCount) ? ntiles : smCount);
    bond_mlp_mma<<<grid, TPB, SMEM_TOTAL>>>(
        bond_feats, atom_feats, global_feats, atom_idx, global_idx, out, n_bond);
}

// round 12
// speedup vs baseline: 1.0602x; 1.0602x over previous
#include <cuda_runtime.h>
#include <cuda_bf16.h>
#include <cstdint>

#define TPB   256
#define M_CTA 256

// ---------------- smem map (bytes; regions 1024-aligned) ----------------
#define OFF_BIAS 0          // 160 floats
#define OFF_W1H  1024       // 4 segs x [64k][64n] bf16, 8192 B each
#define OFF_W1L  33792
#define OFF_W2H  66560
#define OFF_W2L  74752
#define OFF_W3H  82944      // padded to n=64
#define OFF_W3L  91136
#define STAGE_BYTES 99328   // [0, STAGE_BYTES) is the precomputed image
#define OFF_X0H  99328      // X buffer 0: [256 rows][64 cols] bf16 hi
#define OFF_X0L  132096
#define OFF_X1H  164864     // X buffer 1
#define OFF_X1L  197632
#define SMEM_TOTAL 230400

#define SWZ128(bo) ((bo) ^ (((bo) >> 3) & 0x70))

__device__ __align__(1024) unsigned char g_stage[STAGE_BYTES];
__device__ int g_is64;

// ---------------- PTX wrappers ----------------
__device__ __forceinline__ uint32_t smem_u32(const void* p) {
    uint32_t a;
    asm("{ .reg .u64 t; cvta.to.shared.u64 t, %1; cvt.u32.u64 %0, t; }" : "=r"(a) : "l"(p));
    return a;
}
__device__ __forceinline__ void ldsm4(uint32_t r[4], uint32_t a) {
    asm volatile("ldmatrix.sync.aligned.m8n8.x4.shared.b16 {%0,%1,%2,%3}, [%4];"
        : "=r"(r[0]), "=r"(r[1]), "=r"(r[2]), "=r"(r[3]) : "r"(a));
}
__device__ __forceinline__ void ldsm4t(uint32_t r[4], uint32_t a) {
    asm volatile("ldmatrix.sync.aligned.m8n8.x4.trans.shared.b16 {%0,%1,%2,%3}, [%4];"
        : "=r"(r[0]), "=r"(r[1]), "=r"(r[2]), "=r"(r[3]) : "r"(a));
}
__device__ __forceinline__ void mma16816(float c[4], const uint32_t a[4], const uint32_t b[2]) {
    asm volatile("mma.sync.aligned.m16n8k16.row.col.f32.bf16.bf16.f32 "
        "{%0,%1,%2,%3}, {%4,%5,%6,%7}, {%8,%9}, {%0,%1,%2,%3};"
        : "+f"(c[0]), "+f"(c[1]), "+f"(c[2]), "+f"(c[3])
        : "r"(a[0]), "r"(a[1]), "r"(a[2]), "r"(a[3]), "r"(b[0]), "r"(b[1]));
}

// ---------------- numeric helpers ----------------
__device__ __forceinline__ uint32_t pack_hi2(float a, float b) {
    return (__float_as_uint(a) >> 16) | (__float_as_uint(b) & 0xFFFF0000u);
}
__device__ __forceinline__ uint32_t pack_lo2(float a, float b) {
    float ra = a - __uint_as_float(__float_as_uint(a) & 0xFFFF0000u);
    float rb = b - __uint_as_float(__float_as_uint(b) & 0xFFFF0000u);
    return (__float_as_uint(ra) >> 16) | (__float_as_uint(rb) & 0xFFFF0000u);
}
__device__ __forceinline__ float softplus_f(float v) {
    return fmaxf(v, 0.0f) + __logf(1.0f + __expf(-fabsf(v)));
}

// ---------------------------------------------------------------------------
// precompute split-bf16 swizzled weight image + biases; block 0 also detects
// index dtype (int64 vs int32) from odd 32-bit words of atom_idx.
__global__ void stage_weights(const float* __restrict__ W1, const float* __restrict__ b1,
                              const float* __restrict__ W2, const float* __restrict__ b2,
                              const float* __restrict__ W3, const float* __restrict__ b3,
                              const unsigned int* __restrict__ idxprobe) {
    if (blockIdx.x == 0 && threadIdx.x < 32) {
        unsigned ok = __ballot_sync(0xFFFFFFFFu, idxprobe[2 * threadIdx.x + 1] == 0u);
        if (threadIdx.x == 0) g_is64 = (ok == 0xFFFFFFFFu);
    }
    int t = blockIdx.x * blockDim.x + threadIdx.x;
    unsigned char* st = g_stage;
    if (t < 16384) {                       // W1 [256k][64n]
        int n = t & 63, k = t >> 6;
        float v = W1[t];
        int s = k >> 6, kl = k & 63;
        uint32_t bo = SWZ128((uint32_t)(kl * 128 + n * 2));
        float r = v - __uint_as_float(__float_as_uint(v) & 0xFFFF0000u);
        *(unsigned short*)(st + OFF_W1H + s * 8192 + bo) = (unsigned short)(__float_as_uint(v) >> 16);
        *(unsigned short*)(st + OFF_W1L + s * 8192 + bo) = (unsigned short)(__float_as_uint(r) >> 16);
    } else if (t < 20480) {                // W2 [64][64]
        int i = t - 16384;
        int n = i & 63, k = i >> 6;
        float v = W2[i];
        uint32_t bo = SWZ128((uint32_t)(k * 128 + n * 2));
        float r = v - __uint_as_float(__float_as_uint(v) & 0xFFFF0000u);
        *(unsigned short*)(st + OFF_W2H + bo) = (unsigned short)(__float_as_uint(v) >> 16);
        *(unsigned short*)(st + OFF_W2L + bo) = (unsigned short)(__float_as_uint(r) >> 16);
    } else if (t < 24576) {                // W3 [64][32] padded to n=64
        int i = t - 20480;
        int n = i & 63, k = i >> 6;
        float v = (n < 32) ? W3[k * 32 + n] : 0.0f;
        uint32_t bo = SWZ128((uint32_t)(k * 128 + n * 2));
        float r = v - __uint_as_float(__float_as_uint(v) & 0xFFFF0000u);
        *(unsigned short*)(st + OFF_W3H + bo) = (unsigned short)(__float_as_uint(v) >> 16);
        *(unsigned short*)(st + OFF_W3L + bo) = (unsigned short)(__float_as_uint(r) >> 16);
    } else if (t < 24576 + 64) {
        ((float*)(st + OFF_BIAS))[t - 24576] = b1[t - 24576];
    } else if (t < 24576 + 128) {
        ((float*)(st + OFF_BIAS))[t - 24576] = b2[t - 24640];
    } else if (t < 24576 + 160) {
        ((float*)(st + OFF_BIAS))[t - 24576] = b3[t - 24704];
    }
}

// ---------------- cooperative gather ----------------
struct GatherCtx {
    const float* bond; const float* atom; const float* glob;
    const void* aidx; const void* gidx;
    int n_bond; int is64; int lb; int part;
};

template<int SEG>
__device__ __forceinline__ void load_chunk(const GatherCtx& c, long long base,
                                           int r0, float4 v[8]) {
    #pragma unroll
    for (int i = 0; i < 8; i++) {
        const int bl = (r0 + i) * 16 + c.lb;
        const long long gb = base + bl;
        const size_t bond = (size_t)((gb < c.n_bond) ? gb : (c.n_bond - 1));
        size_t row; const float* bp;
        if (SEG == 0) { row = bond; bp = c.bond; }
        else if (SEG == 3) {
            row = c.is64 ? (size_t)((const long long*)c.gidx)[bond]
                         : (size_t)((const int*)c.gidx)[bond];
            bp = c.glob;
        } else {
            row = c.is64 ? (size_t)((const long long*)c.aidx)[2 * bond + (SEG - 1)]
                         : (size_t)((const int*)c.aidx)[2 * bond + (SEG - 1)];
            bp = c.atom;
        }
        v[i] = ((const float4*)(bp + row * 64))[c.part];
    }
}

__device__ __forceinline__ void sts_chunk(char* smem, uint32_t offH, uint32_t offL,
                                          int lb, int part, int r0, const float4 v[8]) {
    #pragma unroll
    for (int i = 0; i < 8; i++) {
        const int bl = (r0 + i) * 16 + lb;
        const uint32_t bo = SWZ128((uint32_t)(bl * 128 + part * 8));
        uint64_t hi = ((uint64_t)pack_hi2(v[i].z, v[i].w) << 32) | pack_hi2(v[i].x, v[i].y);
        uint64_t lo = ((uint64_t)pack_lo2(v[i].z, v[i].w) << 32) | pack_lo2(v[i].x, v[i].y);
        *(uint64_t*)(smem + offH + bo) = hi;
        *(uint64_t*)(smem + offL + bo) = lo;
    }
}

// ---------------- warp-level GEMM (M=32), A from smem: kt in [KT0, KT1) ------
template<int NT, int KT0, int KT1>
__device__ __forceinline__ void gemm_part(uint32_t sb,
                                          uint32_t offAH, uint32_t offAL,
                                          uint32_t offBH, uint32_t offBL,
                                          int m0, int lane, float acc[][4]) {
    #pragma unroll
    for (int kt = KT0; kt < KT1; kt++) {
        const int k0 = kt * 16;
        uint32_t ah[2][4], al[2][4];
        #pragma unroll
        for (int mt = 0; mt < 2; mt++) {
            int row = m0 + mt * 16 + (lane & 15);
            uint32_t bo = (uint32_t)(row * 128 + k0 * 2 + ((lane >> 4) << 4));
            ldsm4(ah[mt], sb + offAH + SWZ128(bo));
            ldsm4(al[mt], sb + offAL + SWZ128(bo));
        }
        #pragma unroll
        for (int nb = 0; nb < NT / 2; nb++) {
            uint32_t bh[4], bl[4];
            int krow = k0 + (lane & 15);
            uint32_t bo = (uint32_t)(krow * 128 + nb * 32 + ((lane >> 4) << 4));
            ldsm4t(bh, sb + offBH + SWZ128(bo));
            ldsm4t(bl, sb + offBL + SWZ128(bo));
            #pragma unroll
            for (int h = 0; h < 2; h++) {
                const uint32_t bfh[2] = { bh[2 * h], bh[2 * h + 1] };
                const uint32_t bfl[2] = { bl[2 * h], bl[2 * h + 1] };
                const int nt = nb * 2 + h;
                #pragma unroll
                for (int mt = 0; mt < 2; mt++) {
                    mma16816(acc[mt * NT + nt], ah[mt], bfh);
                    mma16816(acc[mt * NT + nt], ah[mt], bfl);
                    mma16816(acc[mt * NT + nt], al[mt], bfh);
                }
            }
        }
    }
}

// ---------------- warp-level GEMM (M=32), A from pre-packed fragments --------
// aph/alp: [mt][kt][4] split-bf16 A fragments (packed ONCE after activation).
template<int NT, int KT0, int KT1>
__device__ __forceinline__ void gemm_regA(uint32_t sb,
                                          const uint32_t aph[2][4][4],
                                          const uint32_t alp[2][4][4],
                                          uint32_t offBH, uint32_t offBL,
                                          int lane, float acc[][4]) {
    #pragma unroll
    for (int kt = KT0; kt < KT1; kt++) {
        const int k0 = kt * 16;
        #pragma unroll
        for (int nb = 0; nb < NT / 2; nb++) {
            uint32_t bh[4], bl[4];
            int krow = k0 + (lane & 15);
            uint32_t bo = (uint32_t)(krow * 128 + nb * 32 + ((lane >> 4) << 4));
            ldsm4t(bh, sb + offBH + SWZ128(bo));
            ldsm4t(bl, sb + offBL + SWZ128(bo));
            #pragma unroll
            for (int h2 = 0; h2 < 2; h2++) {
                const uint32_t bfh[2] = { bh[2 * h2], bh[2 * h2 + 1] };
                const uint32_t bfl[2] = { bl[2 * h2], bl[2 * h2 + 1] };
                const int nt = nb * 2 + h2;
                #pragma unroll
                for (int mt = 0; mt < 2; mt++) {
                    mma16816(acc[mt * NT + nt], aph[mt][kt], bfh);
                    mma16816(acc[mt * NT + nt], aph[mt][kt], bfl);
                    mma16816(acc[mt * NT + nt], alp[mt][kt], bfh);
                }
            }
        }
    }
}

// bias + softplus in place on 16 C-fragments (M=32 warp tile)
__device__ __forceinline__ void act_inplace(float acc[][4], const float* bias, int lane) {
    #pragma unroll
    for (int i = 0; i < 16; i++) {
        const int col = (i & 7) * 8 + (lane & 3) * 2;
        const float b0 = bias[col], b1 = bias[col + 1];
        acc[i][0] = softplus_f(acc[i][0] + b0);
        acc[i][1] = softplus_f(acc[i][1] + b1);
        acc[i][2] = softplus_f(acc[i][2] + b0);
        acc[i][3] = softplus_f(acc[i][3] + b1);
    }
}

// pack activated C-fragments into split-bf16 A-fragments (once per layer)
__device__ __forceinline__ void pack_h(const float acc[][4],
                                       uint32_t aph[2][4][4], uint32_t alp[2][4][4]) {
    #pragma unroll
    for (int mt = 0; mt < 2; mt++)
    #pragma unroll
    for (int kt = 0; kt < 4; kt++) {
        const float* t0 = acc[mt * 8 + 2 * kt];
        const float* t1 = acc[mt * 8 + 2 * kt + 1];
        aph[mt][kt][0] = pack_hi2(t0[0], t0[1]);
        aph[mt][kt][1] = pack_hi2(t0[2], t0[3]);
        aph[mt][kt][2] = pack_hi2(t1[0], t1[1]);
        aph[mt][kt][3] = pack_hi2(t1[2], t1[3]);
        alp[mt][kt][0] = pack_lo2(t0[0], t0[1]);
        alp[mt][kt][1] = pack_lo2(t0[2], t0[3]);
        alp[mt][kt][2] = pack_lo2(t1[0], t1[1]);
        alp[mt][kt][3] = pack_lo2(t1[2], t1[3]);
    }
}

// ---------------------------------------------------------------------------
__global__ __launch_bounds__(TPB, 1)
void bond_mlp_mma(const float* __restrict__ bond_feats,
                  const float* __restrict__ atom_feats,
                  const float* __restrict__ global_feats,
                  const void*  __restrict__ atom_idx,
                  const void*  __restrict__ global_idx,
                  float* __restrict__ out, int n_bond)
{
    extern __shared__ char smem[];
    const uint32_t sb = smem_u32(smem);
    const int tid  = threadIdx.x;
    const int wid  = tid >> 5;
    const int lane = tid & 31;
    const int m0   = wid * 32;

    GatherCtx ctx;
    ctx.bond = bond_feats; ctx.atom = atom_feats; ctx.glob = global_feats;
    ctx.aidx = atom_idx;   ctx.gidx = global_idx;
    ctx.n_bond = n_bond;   ctx.is64 = g_is64;
    ctx.lb = tid >> 4;     ctx.part = tid & 15;

    const long long ntiles = (n_bond + M_CTA - 1) / M_CTA;
    long long tile = blockIdx.x;
    long long base = tile * M_CTA;

    float4 v[8];

    // prologue: seg0 of first tile LDGs in flight during the one-time weight copy
    load_chunk<0>(ctx, base, 0, v);
    {
        const float4* src = (const float4*)g_stage;
        float4* dst = (float4*)smem;
        #pragma unroll 5
        for (int i = tid; i < STAGE_BYTES / 16; i += TPB) dst[i] = src[i];
    }
    sts_chunk(smem, OFF_X0H, OFF_X0L, ctx.lb, ctx.part, 0, v);
    load_chunk<0>(ctx, base, 8, v);
    sts_chunk(smem, OFF_X0H, OFF_X0L, ctx.lb, ctx.part, 8, v);
    __syncthreads();

    // persistent tile loop; invariant on entry: X0 holds seg0 of `tile`, synced
    #pragma unroll 1
    while (true) {
        float acc[16][4];
        #pragma unroll
        for (int i = 0; i < 16; i++)
            #pragma unroll
            for (int q = 0; q < 4; q++) acc[i][q] = 0.0f;

        // ---- L1 seg0 (reads X0, prefetch seg1 -> X1) ----
        load_chunk<1>(ctx, base, 0, v);
        gemm_part<8, 0, 2>(sb, OFF_X0H, OFF_X0L, OFF_W1H, OFF_W1L, m0, lane, acc);
        sts_chunk(smem, OFF_X1H, OFF_X1L, ctx.lb, ctx.part, 0, v);
        load_chunk<1>(ctx, base, 8, v);
        gemm_part<8, 2, 4>(sb, OFF_X0H, OFF_X0L, OFF_W1H, OFF_W1L, m0, lane, acc);
        sts_chunk(smem, OFF_X1H, OFF_X1L, ctx.lb, ctx.part, 8, v);
        __syncthreads();

        // ---- seg1 (reads X1, prefetch seg2 -> X0) ----
        load_chunk<2>(ctx, base, 0, v);
        gemm_part<8, 0, 2>(sb, OFF_X1H, OFF_X1L, OFF_W1H + 8192, OFF_W1L + 8192, m0, lane, acc);
        sts_chunk(smem, OFF_X0H, OFF_X0L, ctx.lb, ctx.part, 0, v);
        load_chunk<2>(ctx, base, 8, v);
        gemm_part<8, 2, 4>(sb, OFF_X1H, OFF_X1L, OFF_W1H + 8192, OFF_W1L + 8192, m0, lane, acc);
        sts_chunk(smem, OFF_X0H, OFF_X0L, ctx.lb, ctx.part, 8, v);
        __syncthreads();

        // ---- seg2 (reads X0, prefetch seg3 -> X1) ----
        load_chunk<3>(ctx, base, 0, v);
        gemm_part<8, 0, 2>(sb, OFF_X0H, OFF_X0L, OFF_W1H + 16384, OFF_W1L + 16384, m0, lane, acc);
        sts_chunk(smem, OFF_X1H, OFF_X1L, ctx.lb, ctx.part, 0, v);
        load_chunk<3>(ctx, base, 8, v);
        gemm_part<8, 2, 4>(sb, OFF_X0H, OFF_X0L, OFF_W1H + 16384, OFF_W1L + 16384, m0, lane, acc);
        sts_chunk(smem, OFF_X1H, OFF_X1L, ctx.lb, ctx.part, 8, v);
        __syncthreads();

        // ---- seg3 (reads X1) ----
        gemm_part<8, 0, 4>(sb, OFF_X1H, OFF_X1L, OFF_W1H + 24576, OFF_W1L + 24576, m0, lane, acc);

        // ---- h1 = softplus(acc + b1); pack ONCE to split-bf16 fragments ----
        act_inplace(acc, (const float*)(smem + OFF_BIAS), lane);
        uint32_t aph[2][4][4], alp[2][4][4];
        pack_h(acc, aph, alp);          // acc dead after this

        // ---- L2 (A from packed registers); prefetch next tile seg0 -> X0 ---
        const long long ntile = tile + gridDim.x;
        const bool more = (ntile < ntiles);
        const long long nbase = ntile * M_CTA;

        float acc2[16][4];
        #pragma unroll
        for (int i = 0; i < 16; i++)
            #pragma unroll
            for (int q = 0; q < 4; q++) acc2[i][q] = 0.0f;

        if (more) load_chunk<0>(ctx, nbase, 0, v);
        gemm_regA<8, 0, 2>(sb, aph, alp, OFF_W2H, OFF_W2L, lane, acc2);
        if (more) { sts_chunk(smem, OFF_X0H, OFF_X0L, ctx.lb, ctx.part, 0, v);
                    load_chunk<0>(ctx, nbase, 8, v); }
        gemm_regA<8, 2, 4>(sb, aph, alp, OFF_W2H, OFF_W2L, lane, acc2);
        if (more) sts_chunk(smem, OFF_X0H, OFF_X0L, ctx.lb, ctx.part, 8, v);

        // ---- h2 = softplus(acc2 + b2); pack (reuse fragment regs) ----
        act_inplace(acc2, (const float*)(smem + OFF_BIAS) + 64, lane);
        pack_h(acc2, aph, alp);         // acc2 dead after this

        // ---- L3 (A from packed registers, N=32) ----
        float acc3[8][4];
        #pragma unroll
        for (int i = 0; i < 8; i++)
            #pragma unroll
            for (int q = 0; q < 4; q++) acc3[i][q] = 0.0f;
        gemm_regA<4, 0, 4>(sb, aph, alp, OFF_W3H, OFF_W3L, lane, acc3);

        // ---- output: acc3 + b3 -> global ----
        {
            const float* bias = (const float*)(smem + OFF_BIAS) + 128;
            #pragma unroll
            for (int mt = 0; mt < 2; mt++)
            #pragma unroll
            for (int nt = 0; nt < 4; nt++) {
                const int col = nt * 8 + (lane & 3) * 2;
                const float bv0 = bias[col], bv1 = bias[col + 1];
                #pragma unroll
                for (int h = 0; h < 2; h++) {
                    const int row = m0 + mt * 16 + (lane >> 2) + h * 8;
                    const long long gb = base + row;
                    if (gb < n_bond) {
                        float2 o = make_float2(acc3[mt * 4 + nt][2 * h]     + bv0,
                                               acc3[mt * 4 + nt][2 * h + 1] + bv1);
                        *(float2*)(out + (size_t)gb * 32 + col) = o;
                    }
                }
            }
        }

        if (!more) break;
        tile = ntile; base = nbase;
        __syncthreads();   // X0 (next seg0) visible; X1 seg3 reads complete
    }
}

// ---------------------------------------------------------------------------
extern "C" void kernel_launch(void* const* d_in, const int* in_sizes, int n_in,
                              void* d_out, int out_size)
{
    const float* bond_feats   = (const float*)d_in[0];
    const float* atom_feats   = (const float*)d_in[1];
    const float* global_feats = (const float*)d_in[2];
    const void*  atom_idx     = d_in[3];
    const void*  global_idx   = d_in[4];
    const float* W1 = (const float*)d_in[5];
    const float* b1 = (const float*)d_in[6];
    const float* W2 = (const float*)d_in[7];
    const float* b2 = (const float*)d_in[8];
    const float* W3 = (const float*)d_in[9];
    const float* b3 = (const float*)d_in[10];
    float* out = (float*)d_out;

    const int n_bond = in_sizes[0] / 64;
    const long long ntiles = (n_bond + M_CTA - 1) / M_CTA;

    static int smCount = 0;
    if (!smCount) {
        cudaFuncSetAttribute(bond_mlp_mma,
                             cudaFuncAttributeMaxDynamicSharedMemorySize, SMEM_TOTAL);
        cudaDeviceGetAttribute(&smCount, cudaDevAttrMultiProcessorCount, 0);
        if (smCount <= 0) smCount = 148;
    }

    stage_weights<<<97, 256>>>(W1, b1, W2, b2, W3, b3, (const unsigned int*)atom_idx);

    const int grid = (int)((ntiles < smCount) ? ntiles : smCount);
    bond_mlp_mma<<<grid, TPB, SMEM_TOTAL>>>(
        bond_feats, atom_feats, global_feats, atom_idx, global_idx, out, n_bond);
}